// round 14
// baseline (speedup 1.0000x reference)
#include <cuda_runtime.h>

// Problem constants
#define BATCH 128
#define CIN   17
#define TIN   4096
#define C1    32
#define T1    2048   // after pool1
#define C2    64
#define NN    1024   // nodes after pool2
#define DG    16     // GAT out dim

typedef unsigned long long ull;

// ---- packed f32x2 helpers (FFMA2 path; ptxas won't auto-fuse) ----
__device__ __forceinline__ ull pack2(float lo, float hi) {
    ull v; asm("mov.b64 %0, {%1, %2};" : "=l"(v) : "f"(lo), "f"(hi)); return v;
}
__device__ __forceinline__ void unpack2(ull v, float& lo, float& hi) {
    asm("mov.b64 {%0, %1}, %2;" : "=f"(lo), "=f"(hi) : "l"(v));
}
__device__ __forceinline__ ull ffma2(ull a, ull b, ull c) {
    ull d; asm("fma.rn.f32x2 %0, %1, %2, %3;" : "=l"(d) : "l"(a), "l"(b), "l"(c));
    return d;
}

// padded scan index: stride-17 layout kills the 16-way bank conflict
__device__ __forceinline__ int IDXf(int j) { return j + (j >> 4); }

// ---- scratch (static device allocations; no cudaMalloc anywhere) ----
__device__ float g_h1[BATCH * C1 * T1];     // 33.5 MB
__device__ float g_hw[BATCH * NN * DG];     // 8.4 MB
__device__ float g_ssrc[BATCH * NN];
__device__ float g_sdst[BATCH * NN];

// ============================================================
// conv1: x[b][17][4096] -> relu -> maxpool2 -> g_h1[b][32][2048]
// Raw (un-duplicated) inputs in smem: 48B in + 80B w per thread-channel.
// Dup pairs rebuilt in registers (alu pipe has headroom).
// ============================================================
__global__ __launch_bounds__(128) void k_conv1(const float* __restrict__ x,
                                               const float* __restrict__ w,
                                               const float* __restrict__ bias) {
    __shared__ __align__(16) float sinp[CIN][132];  // raw input, 9 KB
    __shared__ __align__(16) float sw[85 * 32];     // [(c*5+k)][oc] transposed
    const int b   = blockIdx.y;
    const int t0  = blockIdx.x * 128;
    const int tid = threadIdx.x;

    // weights: 2720 floats = 680 float4, scatter to transposed layout
    {
        const float4* w4 = (const float4*)w;
        for (int i = tid; i < 680; i += 128) {
            float4 v = w4[i];
            int f = i * 4;
#pragma unroll
            for (int u = 0; u < 4; u++) {
                int ff = f + u;
                int oc = ff / 85, r = ff - oc * 85;
                sw[r * 32 + oc] = (&v.x)[u];
            }
        }
    }
    // input body: 17 rows x 32 float4 (aligned global reads, scalar smem writes)
    for (int i = tid; i < 17 * 32; i += 128) {
        int c = i >> 5, iv = i & 31;
        float4 v = *(const float4*)&x[(b * CIN + c) * TIN + t0 + iv * 4];
        int p = 2 + iv * 4;
        sinp[c][p]     = v.x;
        sinp[c][p + 1] = v.y;
        sinp[c][p + 2] = v.z;
        sinp[c][p + 3] = v.w;
    }
    // halo: 2 each side per row
    if (tid < 68) {
        int c = tid >> 2, u = tid & 3;
        int p = (u < 2) ? u : (128 + u);           // {0,1,130,131}
        int t = t0 - 2 + p;
        sinp[c][p] = (t >= 0 && t < TIN) ? x[(b * CIN + c) * TIN + t] : 0.f;
    }
    __syncthreads();

    const int ocg = tid & 7, pg = tid >> 3;
    const int oc0 = ocg * 4;                       // 4 ocs = 2 packed pairs
    const int cp0 = pg * 8;                        // 8 conv positions (16B-aligned)

    ull acc2[2][8];
    {
        ull b0 = pack2(bias[oc0],     bias[oc0 + 1]);
        ull b1 = pack2(bias[oc0 + 2], bias[oc0 + 3]);
#pragma unroll
        for (int p = 0; p < 8; p++) { acc2[0][p] = b0; acc2[1][p] = b1; }
    }

    for (int c = 0; c < CIN; c++) {
        const float4* ip = (const float4*)&sinp[c][cp0];
        float4 v0 = ip[0], v1 = ip[1], v2 = ip[2];  // 3x LDS.128 = 48B
        ull bb[12];
        bb[0]  = pack2(v0.x, v0.x); bb[1]  = pack2(v0.y, v0.y);
        bb[2]  = pack2(v0.z, v0.z); bb[3]  = pack2(v0.w, v0.w);
        bb[4]  = pack2(v1.x, v1.x); bb[5]  = pack2(v1.y, v1.y);
        bb[6]  = pack2(v1.z, v1.z); bb[7]  = pack2(v1.w, v1.w);
        bb[8]  = pack2(v2.x, v2.x); bb[9]  = pack2(v2.y, v2.y);
        bb[10] = pack2(v2.z, v2.z); bb[11] = pack2(v2.w, v2.w);
#pragma unroll
        for (int k = 0; k < 5; k++) {              // 5x LDS.128 = 80B
            ulonglong2 wv = *reinterpret_cast<const ulonglong2*>(
                &sw[(c * 5 + k) * 32 + oc0]);
#pragma unroll
            for (int p = 0; p < 8; p++) {
                acc2[0][p] = ffma2(bb[p + k], wv.x, acc2[0][p]);
                acc2[1][p] = ffma2(bb[p + k], wv.y, acc2[1][p]);
            }
        }
    }

    const int pbase = blockIdx.x * 64 + pg * 4;
#pragma unroll
    for (int a2 = 0; a2 < 2; a2++)
#pragma unroll
        for (int q = 0; q < 4; q++) {
            float lo0, hi0, lo1, hi1;
            unpack2(acc2[a2][2 * q],     lo0, hi0);
            unpack2(acc2[a2][2 * q + 1], lo1, hi1);
            int oc = oc0 + 2 * a2;
            g_h1[(b * C1 + oc)     * T1 + pbase + q] = fmaxf(fmaxf(lo0, lo1), 0.f);
            g_h1[(b * C1 + oc + 1) * T1 + pbase + q] = fmaxf(fmaxf(hi0, hi1), 0.f);
        }
}

// ============================================================
// conv2 FUSED: g_h1 -> conv(32->64,k5) -> relu -> maxpool2 -> (smem)
//   -> hw = h2 @ gat_wT, s_src, s_dst
// Remapped: 16 ocg x 16 pg (4 ocs x 8 positions per thread) so weight
// bytes amortize over 2x positions: 128B total per thread-channel.
// ============================================================
struct Conv2Sm {
    union {
        float sinp[C1][132];             // 16896 B (phase 1, raw)
        float h2s[64][65];               // 16640 B (epilogue, pad 65)
    } A;
    union {
        float sw[160 * 64];              // 40960 B ([(c*5+k)][oc], all 64 ocs)
        struct {
            float4 wt4[64 * 4];          //  4096 B (epilogue: wT[d][o])
            float  red[2][64][4];        //  2048 B
        } ep;
    } B;
};

extern __shared__ __align__(16) char c2raw[];

__global__ __launch_bounds__(256) void k_conv2(const float* __restrict__ w,
                                               const float* __restrict__ bias,
                                               const float* __restrict__ gw,
                                               const float* __restrict__ asrc,
                                               const float* __restrict__ adst) {
    Conv2Sm& cs = *reinterpret_cast<Conv2Sm*>(c2raw);
    const int b   = blockIdx.y;
    const int t0  = blockIdx.x * 128;
    const int tid = threadIdx.x;

    // weights: 64*160 floats = 2560 float4, scatter to [(c*5+k)*64 + oc]
    {
        const float4* w4 = (const float4*)w;
        for (int i = tid; i < 2560; i += 256) {
            float4 v = w4[i];
            int f = i * 4;
#pragma unroll
            for (int u = 0; u < 4; u++) {
                int ff = f + u;
                int oc = ff / 160, r = ff - oc * 160;
                cs.B.sw[r * 64 + oc] = (&v.x)[u];
            }
        }
    }
    // input body: 32 rows x 32 float4
    for (int i = tid; i < 32 * 32; i += 256) {
        int c = i >> 5, iv = i & 31;
        float4 v = *(const float4*)&g_h1[(b * C1 + c) * T1 + t0 + iv * 4];
        int p = 2 + iv * 4;
        cs.A.sinp[c][p]     = v.x;
        cs.A.sinp[c][p + 1] = v.y;
        cs.A.sinp[c][p + 2] = v.z;
        cs.A.sinp[c][p + 3] = v.w;
    }
    if (tid < 128) {
        int c = tid >> 2, u = tid & 3;
        int p = (u < 2) ? u : (128 + u);
        int t = t0 - 2 + p;
        cs.A.sinp[c][p] = (t >= 0 && t < T1) ? g_h1[(b * C1 + c) * T1 + t] : 0.f;
    }
    __syncthreads();

    const int ocg = tid & 15, pg = tid >> 4;       // 16 oc-groups x 16 pos-groups
    const int oc0 = ocg * 4;                       // covers all 64 ocs
    const int cp0 = pg * 8;                        // 8 conv positions

    ull acc2[2][8];
    {
        ull b0 = pack2(bias[oc0],     bias[oc0 + 1]);
        ull b1 = pack2(bias[oc0 + 2], bias[oc0 + 3]);
#pragma unroll
        for (int p = 0; p < 8; p++) { acc2[0][p] = b0; acc2[1][p] = b1; }
    }

    for (int c = 0; c < C1; c++) {
        const float4* ip = (const float4*)&cs.A.sinp[c][cp0];
        float4 v0 = ip[0], v1 = ip[1], v2 = ip[2];  // 48B
        ull bb[12];
        bb[0]  = pack2(v0.x, v0.x); bb[1]  = pack2(v0.y, v0.y);
        bb[2]  = pack2(v0.z, v0.z); bb[3]  = pack2(v0.w, v0.w);
        bb[4]  = pack2(v1.x, v1.x); bb[5]  = pack2(v1.y, v1.y);
        bb[6]  = pack2(v1.z, v1.z); bb[7]  = pack2(v1.w, v1.w);
        bb[8]  = pack2(v2.x, v2.x); bb[9]  = pack2(v2.y, v2.y);
        bb[10] = pack2(v2.z, v2.z); bb[11] = pack2(v2.w, v2.w);
#pragma unroll
        for (int k = 0; k < 5; k++) {              // 80B weights
            ulonglong2 wv = *reinterpret_cast<const ulonglong2*>(
                &cs.B.sw[(c * 5 + k) * 64 + oc0]);
#pragma unroll
            for (int p = 0; p < 8; p++) {
                acc2[0][p] = ffma2(bb[p + k], wv.x, acc2[0][p]);
                acc2[1][p] = ffma2(bb[p + k], wv.y, acc2[1][p]);
            }
        }
    }
    __syncthreads();                               // all sinp/sw reads done

    // pooled relu -> smem h2 tile; concurrently load wT into B union
#pragma unroll
    for (int a2 = 0; a2 < 2; a2++)
#pragma unroll
        for (int q = 0; q < 4; q++) {
            float lo0, hi0, lo1, hi1;
            unpack2(acc2[a2][2 * q],     lo0, hi0);
            unpack2(acc2[a2][2 * q + 1], lo1, hi1);
            int node = pg * 4 + q;
            int oc   = oc0 + 2 * a2;
            cs.A.h2s[node][oc]     = fmaxf(fmaxf(lo0, lo1), 0.f);
            cs.A.h2s[node][oc + 1] = fmaxf(fmaxf(hi0, hi1), 0.f);
        }
    {
        float* wt = (float*)cs.B.ep.wt4;           // wt[d*16+o]
        for (int i = tid; i < 1024; i += 256) {
            int o = i >> 6, d = i & 63;
            wt[d * 16 + o] = gw[i];
        }
    }
    __syncthreads();

    // epilogue: hw[node][og*4..+3] = sum_d h2s[node][d] * wT[d][..]
    const int node = tid & 63;
    const int og   = tid >> 6;
    float acc[4] = {0.f, 0.f, 0.f, 0.f};
#pragma unroll 4
    for (int d = 0; d < 64; d++) {
        float v = cs.A.h2s[node][d];
        float4 w4 = cs.B.ep.wt4[d * 4 + og];
        acc[0] += v * w4.x; acc[1] += v * w4.y;
        acc[2] += v * w4.z; acc[3] += v * w4.w;
    }
    const int ngl = blockIdx.x * 64 + node;
    ((float4*)&g_hw[((size_t)b * NN + ngl) * DG])[og] =
        make_float4(acc[0], acc[1], acc[2], acc[3]);

    float ps = 0.f, pd = 0.f;
#pragma unroll
    for (int u = 0; u < 4; u++) {
        ps += acc[u] * __ldg(&asrc[og * 4 + u]);
        pd += acc[u] * __ldg(&adst[og * 4 + u]);
    }
    cs.B.ep.red[0][node][og] = ps;
    cs.B.ep.red[1][node][og] = pd;
    __syncthreads();
    if (tid < 64) {
        float s = cs.B.ep.red[0][tid][0] + cs.B.ep.red[0][tid][1]
                + cs.B.ep.red[0][tid][2] + cs.B.ep.red[0][tid][3];
        float d = cs.B.ep.red[1][tid][0] + cs.B.ep.red[1][tid][1]
                + cs.B.ep.red[1][tid][2] + cs.B.ep.red[1][tid][3];
        g_ssrc[b * NN + blockIdx.x * 64 + tid] = s;
        g_sdst[b * NN + blockIdx.x * 64 + tid] = d;
    }
}

// ============================================================
// Fused factorized GAT + node-mean + FC. One block per batch sample.
// (unchanged from R11)
// ============================================================
struct GatSmem {
    float key[NN];              // sorted ss
    int   idx[NN];              // permutation
    float scan[17][1090];       // padded rows (IDXf), reused prefix/suffix
    float wtot[17][2];          // per-row warp totals for chunk combine
    float wred[32][DG];         // per-warp partial pooled sums
    float pooled[DG];
};

__global__ __launch_bounds__(1024) void k_gat2(const float* __restrict__ gat_b,
                                               const float* __restrict__ fcw,
                                               const float* __restrict__ fcb,
                                               float* __restrict__ out) {
    extern __shared__ __align__(16) char smraw[];
    GatSmem& sm = *reinterpret_cast<GatSmem*>(smraw);
    const int b   = blockIdx.x;
    const int tid = threadIdx.x;

    sm.key[tid] = g_ssrc[b * NN + tid];
    sm.idx[tid] = tid;

    // bitonic sort ascending (key, idx)
    for (int k = 2; k <= NN; k <<= 1) {
        for (int j = k >> 1; j > 0; j >>= 1) {
            __syncthreads();
            int partner = tid ^ j;
            if (partner > tid) {
                bool up = ((tid & k) == 0);
                float k0 = sm.key[tid], k1 = sm.key[partner];
                if ((k0 > k1) == up) {
                    sm.key[tid] = k1; sm.key[partner] = k0;
                    int t0 = sm.idx[tid];
                    sm.idx[tid] = sm.idx[partner];
                    sm.idx[partner] = t0;
                }
            }
        }
    }
    __syncthreads();

    const float Mss = sm.key[NN - 1];
    const int   i   = tid;
    const float sd  = g_sdst[b * NN + i];
    const float ssi = g_ssrc[b * NN + i];
    const float msd = sd + Mss;
    const float m   = (msd >= 0.f) ? msd : 0.2f * msd;

    int lo = 0, hi = NN;
    {
        const float thr = -sd;
        while (lo < hi) {
            int mid = (lo + hi) >> 1;
            if (sm.key[mid] < thr) lo = mid + 1; else hi = mid;
        }
    }
    const int kth  = lo;
    const int kthx = IDXf(kth);
    const int tix  = IDXf(tid);

    // scan-worker coordinates
    const int sr   = tid >> 6;                 // row 0..15
    const int sc   = tid & 63;                 // chunk within row
    const int lane = sc & 31;
    const int wir  = sc >> 5;                  // warp-in-row
    const int rb   = sc * 17;                  // IDXf(sc*16)

    float num[16];
    float den;

    // ======== Phase B: exclusive prefix of exp(0.2*(ss_j - Mss)) * hv ========
    {
        float bj = __expf(0.2f * (sm.key[tid] - Mss));
        const float4* hp = (const float4*)&g_hw[((size_t)b * NN + sm.idx[tid]) * DG];
        float4 h0 = hp[0], h1 = hp[1], h2 = hp[2], h3 = hp[3];
        sm.scan[0][tix]  = bj * h0.x; sm.scan[1][tix]  = bj * h0.y;
        sm.scan[2][tix]  = bj * h0.z; sm.scan[3][tix]  = bj * h0.w;
        sm.scan[4][tix]  = bj * h1.x; sm.scan[5][tix]  = bj * h1.y;
        sm.scan[6][tix]  = bj * h1.z; sm.scan[7][tix]  = bj * h1.w;
        sm.scan[8][tix]  = bj * h2.x; sm.scan[9][tix]  = bj * h2.y;
        sm.scan[10][tix] = bj * h2.z; sm.scan[11][tix] = bj * h2.w;
        sm.scan[12][tix] = bj * h3.x; sm.scan[13][tix] = bj * h3.y;
        sm.scan[14][tix] = bj * h3.z; sm.scan[15][tix] = bj * h3.w;
        sm.scan[16][tix] = bj;
    }
    __syncthreads();
    {
        // pass 1: chunk sums + warp inclusive scans
        float* row = sm.scan[sr];
        float s = 0.f;
#pragma unroll
        for (int u = 0; u < 16; u++) s += row[rb + u];
        float inc = s;
#pragma unroll
        for (int o = 1; o < 32; o <<= 1) {
            float v = __shfl_up_sync(0xffffffffu, inc, o);
            if (lane >= o) inc += v;
        }
        if (lane == 31) sm.wtot[sr][wir] = inc;

        float s2 = 0.f, inc2 = 0.f;
        if (tid < 64) {                            // den row (16), warps 0-1
            float* drow = sm.scan[16];
            int drb = tid * 17;
#pragma unroll
            for (int u = 0; u < 16; u++) s2 += drow[drb + u];
            inc2 = s2;
#pragma unroll
            for (int o = 1; o < 32; o <<= 1) {
                float v = __shfl_up_sync(0xffffffffu, inc2, o);
                if ((tid & 31) >= o) inc2 += v;
            }
            if ((tid & 31) == 31) sm.wtot[16][tid >> 5] = inc2;
        }
        __syncthreads();

        // pass 2: apply exclusive offsets
        float off = inc - s + ((wir == 1) ? sm.wtot[sr][0] : 0.f);
        float acc = off;
#pragma unroll
        for (int u = 0; u < 16; u++) {
            float t = row[rb + u]; row[rb + u] = acc; acc += t;
        }
        if (sc == 63) row[IDXf(NN)] = acc;
        if (tid < 64) {
            float* drow = sm.scan[16];
            int drb = tid * 17;
            float off2 = inc2 - s2 + ((tid >= 32) ? sm.wtot[16][0] : 0.f);
            float acc2v = off2;
#pragma unroll
            for (int u = 0; u < 16; u++) {
                float t = drow[drb + u]; drow[drb + u] = acc2v; acc2v += t;
            }
            if (tid == 63) drow[IDXf(NN)] = acc2v;
        }
    }
    __syncthreads();
    {
        float wB = __expf(0.2f * msd - m);
#pragma unroll
        for (int o = 0; o < 16; o++) num[o] = wB * sm.scan[o][kthx];
        den = wB * sm.scan[16][kthx];
    }
    __syncthreads();                               // before buffer reuse

    // ======== Phase A: inclusive suffix of exp(ss_j - Mss) * hv ========
    {
        float aj = __expf(sm.key[tid] - Mss);
        const float4* hp = (const float4*)&g_hw[((size_t)b * NN + sm.idx[tid]) * DG];
        float4 h0 = hp[0], h1 = hp[1], h2 = hp[2], h3 = hp[3];
        sm.scan[0][tix]  = aj * h0.x; sm.scan[1][tix]  = aj * h0.y;
        sm.scan[2][tix]  = aj * h0.z; sm.scan[3][tix]  = aj * h0.w;
        sm.scan[4][tix]  = aj * h1.x; sm.scan[5][tix]  = aj * h1.y;
        sm.scan[6][tix]  = aj * h1.z; sm.scan[7][tix]  = aj * h1.w;
        sm.scan[8][tix]  = aj * h2.x; sm.scan[9][tix]  = aj * h2.y;
        sm.scan[10][tix] = aj * h2.z; sm.scan[11][tix] = aj * h2.w;
        sm.scan[12][tix] = aj * h3.x; sm.scan[13][tix] = aj * h3.y;
        sm.scan[14][tix] = aj * h3.z; sm.scan[15][tix] = aj * h3.w;
        sm.scan[16][tix] = aj;
    }
    __syncthreads();
    {
        float* row = sm.scan[sr];
        float s = 0.f;
#pragma unroll
        for (int u = 0; u < 16; u++) s += row[rb + u];
        float inc = s;                             // suffix scan within warp
#pragma unroll
        for (int o = 1; o < 32; o <<= 1) {
            float v = __shfl_down_sync(0xffffffffu, inc, o);
            if (lane < 32 - o) inc += v;
        }
        if (lane == 0) sm.wtot[sr][wir] = inc;

        float s2 = 0.f, inc2 = 0.f;
        if (tid < 64) {
            float* drow = sm.scan[16];
            int drb = tid * 17;
#pragma unroll
            for (int u = 0; u < 16; u++) s2 += drow[drb + u];
            inc2 = s2;
#pragma unroll
            for (int o = 1; o < 32; o <<= 1) {
                float v = __shfl_down_sync(0xffffffffu, inc2, o);
                if ((tid & 31) < 32 - o) inc2 += v;
            }
            if ((tid & 31) == 0) sm.wtot[16][tid >> 5] = inc2;
        }
        __syncthreads();

        float off = inc - s + ((wir == 0) ? sm.wtot[sr][1] : 0.f);
        float acc = off;
#pragma unroll
        for (int u = 15; u >= 0; u--) {
            acc += row[rb + u]; row[rb + u] = acc;
        }
        if (sc == 63) row[IDXf(NN)] = 0.f;
        if (tid < 64) {
            float* drow = sm.scan[16];
            int drb = tid * 17;
            float off2 = inc2 - s2 + ((tid < 32) ? sm.wtot[16][1] : 0.f);
            float acc2v = off2;
#pragma unroll
            for (int u = 15; u >= 0; u--) {
                acc2v += drow[drb + u]; drow[drb + u] = acc2v;
            }
            if (tid == 63) drow[IDXf(NN)] = 0.f;
        }
    }
    __syncthreads();
    {
        float wA = __expf(msd - m);
#pragma unroll
        for (int o = 0; o < 16; o++) num[o] += wA * sm.scan[o][kthx];
        den += wA * sm.scan[16][kthx];
    }

    // duplicated self-loop (PyG add_self_loops on dense edge list)
    {
        float e = sd + ssi;
        e = (e >= 0.f) ? e : 0.2f * e;
        float ws = __expf(e - m);
        den += ws;
        const float4* hp = (const float4*)&g_hw[((size_t)b * NN + i) * DG];
        float4 h0 = hp[0], h1 = hp[1], h2 = hp[2], h3 = hp[3];
        num[0]  += ws * h0.x; num[1]  += ws * h0.y; num[2]  += ws * h0.z; num[3]  += ws * h0.w;
        num[4]  += ws * h1.x; num[5]  += ws * h1.y; num[6]  += ws * h1.z; num[7]  += ws * h1.w;
        num[8]  += ws * h2.x; num[9]  += ws * h2.y; num[10] += ws * h2.z; num[11] += ws * h2.w;
        num[12] += ws * h3.x; num[13] += ws * h3.y; num[14] += ws * h3.z; num[15] += ws * h3.w;
    }

    const float inv = 1.f / den;
#pragma unroll
    for (int o = 0; o < 16; o++) num[o] *= inv;

    // block reduce over 1024 nodes -> pooled[16] -> fc -> out[b][2]
#pragma unroll
    for (int o = 0; o < 16; o++) {
        float v = num[o];
        v += __shfl_xor_sync(0xffffffffu, v, 16);
        v += __shfl_xor_sync(0xffffffffu, v, 8);
        v += __shfl_xor_sync(0xffffffffu, v, 4);
        v += __shfl_xor_sync(0xffffffffu, v, 2);
        v += __shfl_xor_sync(0xffffffffu, v, 1);
        if ((tid & 31) == 0) sm.wred[tid >> 5][o] = v;
    }
    __syncthreads();
    if (tid < 16) {
        float s = 0.f;
        for (int w = 0; w < 32; w++) s += sm.wred[w][tid];
        sm.pooled[tid] = s * (1.0f / (float)NN) + __ldg(&gat_b[tid]);
    }
    __syncthreads();
    if (tid < 2) {
        float r = __ldg(&fcb[tid]);
#pragma unroll
        for (int o = 0; o < 16; o++) r += sm.pooled[o] * __ldg(&fcw[tid * 16 + o]);
        out[b * 2 + tid] = r;
    }
}

extern "C" void kernel_launch(void* const* d_in, const int* in_sizes, int n_in,
                              void* d_out, int out_size) {
    const float* x    = (const float*)d_in[0];
    const float* c1w  = (const float*)d_in[1];
    const float* c1b  = (const float*)d_in[2];
    const float* c2w  = (const float*)d_in[3];
    const float* c2b  = (const float*)d_in[4];
    const float* gw   = (const float*)d_in[5];
    const float* asrc = (const float*)d_in[6];
    const float* adst = (const float*)d_in[7];
    const float* gb   = (const float*)d_in[8];
    const float* fcw  = (const float*)d_in[9];
    const float* fcb  = (const float*)d_in[10];
    float* out = (float*)d_out;

    k_conv1<<<dim3(32, BATCH), 128>>>(x, c1w, c1b);

    cudaFuncSetAttribute(k_conv2, cudaFuncAttributeMaxDynamicSharedMemorySize,
                         (int)sizeof(Conv2Sm));
    k_conv2<<<dim3(16, BATCH), 256, sizeof(Conv2Sm)>>>(c2w, c2b, gw, asrc, adst);

    cudaFuncSetAttribute(k_gat2, cudaFuncAttributeMaxDynamicSharedMemorySize,
                         (int)sizeof(GatSmem));
    k_gat2<<<BATCH, 1024, sizeof(GatSmem)>>>(gb, fcw, fcb, out);
}

// round 17
// speedup vs baseline: 1.3350x; 1.3350x over previous
#include <cuda_runtime.h>
#include <cuda_bf16.h>
#include <cstdint>

#define BATCH 128
#define CIN 17
#define TIN 4096
#define C1 32
#define T1 2048
#define C2 64
#define NN 1024
#define DG 16
#define WST 164
#define H1W 132

typedef unsigned long long ull;
typedef unsigned short u16;

__device__ __forceinline__ ull pack2(float lo, float hi) {
    ull v; asm("mov.b64 %0, {%1, %2};" : "=l"(v) : "f"(lo), "f"(hi)); return v;
}
__device__ __forceinline__ void unpack2(ull v, float& lo, float& hi) {
    asm("mov.b64 {%0, %1}, %2;" : "=f"(lo), "=f"(hi) : "l"(v));
}
__device__ __forceinline__ ull ffma2(ull a, ull b, ull c) {
    ull d; asm("fma.rn.f32x2 %0, %1, %2, %3;" : "=l"(d) : "l"(a), "l"(b), "l"(c));
    return d;
}
__device__ __forceinline__ int IDXf(int j) { return j + (j >> 4); }
__device__ __forceinline__ void split_bf16(float v, u16& h, u16& l) {
    __nv_bfloat16 hb = __float2bfloat16(v);
    h = *reinterpret_cast<u16*>(&hb);
    __nv_bfloat16 lb = __float2bfloat16(v - __uint_as_float(((uint32_t)h) << 16));
    l = *reinterpret_cast<u16*>(&lb);
}
#define MMA(Cf, A, B0, B1) \
  asm volatile("mma.sync.aligned.m16n8k16.row.col.f32.bf16.bf16.f32 " \
    "{%0,%1,%2,%3}, {%4,%5,%6,%7}, {%8,%9}, {%0,%1,%2,%3};" \
    : "+f"(Cf[0]), "+f"(Cf[1]), "+f"(Cf[2]), "+f"(Cf[3]) \
    : "r"(A[0]), "r"(A[1]), "r"(A[2]), "r"(A[3]), "r"(B0), "r"(B1))

__device__ __align__(16) u16 g_h1h[BATCH * C1 * T1];
__device__ __align__(16) u16 g_h1l[BATCH * C1 * T1];
__device__ __align__(16) u16 g_Wh[C2 * WST];
__device__ __align__(16) u16 g_Wl[C2 * WST];
__device__ float g_hw[BATCH * NN * DG];
__device__ float g_ssrc[BATCH * NN];
__device__ float g_sdst[BATCH * NN];

// conv1 -> relu -> pool -> h1 as bf16 hi/lo
__global__ __launch_bounds__(128) void k_conv1(const float* __restrict__ x,
                                               const float* __restrict__ w,
                                               const float* __restrict__ bias) {
    __shared__ __align__(16) float sinp[CIN][132];
    __shared__ __align__(16) float sw[85 * 32];
    const int b = blockIdx.y, t0 = blockIdx.x * 128, tid = threadIdx.x;
    {
        const float4* w4 = (const float4*)w;
        for (int i = tid; i < 680; i += 128) {
            float4 v = w4[i]; int f = i * 4;
#pragma unroll
            for (int u = 0; u < 4; u++) {
                int ff = f + u, oc = ff / 85, r = ff - oc * 85;
                sw[r * 32 + oc] = (&v.x)[u];
            }
        }
    }
    for (int i = tid; i < 17 * 32; i += 128) {
        int c = i >> 5, iv = i & 31;
        float4 v = *(const float4*)&x[(b * CIN + c) * TIN + t0 + iv * 4];
        int p = 2 + iv * 4;
        sinp[c][p] = v.x; sinp[c][p+1] = v.y; sinp[c][p+2] = v.z; sinp[c][p+3] = v.w;
    }
    if (tid < 68) {
        int c = tid >> 2, u = tid & 3;
        int p = (u < 2) ? u : (128 + u);
        int t = t0 - 2 + p;
        sinp[c][p] = (t >= 0 && t < TIN) ? x[(b * CIN + c) * TIN + t] : 0.f;
    }
    __syncthreads();
    const int ocg = tid & 7, pg = tid >> 3;
    const int oc0 = ocg * 4, cp0 = pg * 8;
    ull acc2[2][8];
    {
        ull b0 = pack2(bias[oc0], bias[oc0+1]), b1 = pack2(bias[oc0+2], bias[oc0+3]);
#pragma unroll
        for (int p = 0; p < 8; p++) { acc2[0][p] = b0; acc2[1][p] = b1; }
    }
    for (int c = 0; c < CIN; c++) {
        const float4* ip = (const float4*)&sinp[c][cp0];
        float4 v0 = ip[0], v1 = ip[1], v2 = ip[2];
        ull bb[12];
        bb[0]=pack2(v0.x,v0.x); bb[1]=pack2(v0.y,v0.y); bb[2]=pack2(v0.z,v0.z); bb[3]=pack2(v0.w,v0.w);
        bb[4]=pack2(v1.x,v1.x); bb[5]=pack2(v1.y,v1.y); bb[6]=pack2(v1.z,v1.z); bb[7]=pack2(v1.w,v1.w);
        bb[8]=pack2(v2.x,v2.x); bb[9]=pack2(v2.y,v2.y); bb[10]=pack2(v2.z,v2.z); bb[11]=pack2(v2.w,v2.w);
#pragma unroll
        for (int k = 0; k < 5; k++) {
            ulonglong2 wv = *reinterpret_cast<const ulonglong2*>(&sw[(c*5+k)*32 + oc0]);
#pragma unroll
            for (int p = 0; p < 8; p++) {
                acc2[0][p] = ffma2(bb[p+k], wv.x, acc2[0][p]);
                acc2[1][p] = ffma2(bb[p+k], wv.y, acc2[1][p]);
            }
        }
    }
    const int pbase = blockIdx.x * 64 + pg * 4;
#pragma unroll
    for (int a2 = 0; a2 < 2; a2++)
#pragma unroll
        for (int q = 0; q < 4; q++) {
            float lo0, hi0, lo1, hi1;
            unpack2(acc2[a2][2*q], lo0, hi0);
            unpack2(acc2[a2][2*q+1], lo1, hi1);
            int oc = oc0 + 2 * a2;
            float va = fmaxf(fmaxf(lo0, lo1), 0.f), vb = fmaxf(fmaxf(hi0, hi1), 0.f);
            u16 h, l;
            int ia = (b*C1+oc)*T1 + pbase + q;
            split_bf16(va, h, l); g_h1h[ia] = h; g_h1l[ia] = l;
            int ib = ia + T1;
            split_bf16(vb, h, l); g_h1h[ib] = h; g_h1l[ib] = l;
        }
}

__global__ void k_prep(const float* __restrict__ w) {
    int i = blockIdx.x * 256 + threadIdx.x;
    if (i < 64 * 160) {
        int oc = i / 160, k = i - oc * 160;
        u16 h, l; split_bf16(w[i], h, l);
        g_Wh[oc * WST + k] = h; g_Wl[oc * WST + k] = l;
    }
}

// conv2 on HMMA: D'[64oc][128pos] = W[oc][160] * X[160][pos], implicit im2col
extern __shared__ __align__(16) char c2sm[];
#define C2SM_TOT 58880

__global__ __launch_bounds__(128) void k_conv2_mma(const float* __restrict__ bias,
                                                   const float* __restrict__ gw,
                                                   const float* __restrict__ asrc,
                                                   const float* __restrict__ adst) {
    __shared__ float s_wt[1024];
    __shared__ float s_red[2][64][2];
    __shared__ float s_bias[64];
    const int b = blockIdx.y, t0 = blockIdx.x * 128, tid = threadIdx.x;
    const int lane = tid & 31, warp = tid >> 5;
    u16* h1h = (u16*)(c2sm);
    u16* h1l = (u16*)(c2sm + 8448);
    u16* swh = (u16*)(c2sm + 16896);
    u16* swl = (u16*)(c2sm + 37888);
    {
        const float4* s0 = (const float4*)g_Wh;
        const float4* s1 = (const float4*)g_Wl;
        float4* d0 = (float4*)swh; float4* d1 = (float4*)swl;
        for (int i = tid; i < 1312; i += 128) { d0[i] = s0[i]; d1[i] = s1[i]; }
    }
    {
        const size_t rb = (size_t)b * C1 * T1;
        for (int i = tid; i < 1024; i += 128) {
            int c = i >> 5, j = i & 31, p = 2 + j * 4;
            ull vh = *(const ull*)&g_h1h[rb + (size_t)c * T1 + t0 + j * 4];
            ull vl = *(const ull*)&g_h1l[rb + (size_t)c * T1 + t0 + j * 4];
            *(uint32_t*)&h1h[c * H1W + p] = (uint32_t)vh;
            *(uint32_t*)&h1h[c * H1W + p + 2] = (uint32_t)(vh >> 32);
            *(uint32_t*)&h1l[c * H1W + p] = (uint32_t)vl;
            *(uint32_t*)&h1l[c * H1W + p + 2] = (uint32_t)(vl >> 32);
        }
        int c = tid >> 2, e = tid & 3;
        int p = (e < 2) ? e : (128 + e);
        int t = t0 - 2 + p;
        u16 vh = 0, vl = 0;
        if (t >= 0 && t < T1) {
            vh = g_h1h[rb + (size_t)c * T1 + t];
            vl = g_h1l[rb + (size_t)c * T1 + t];
        }
        h1h[c * H1W + p] = vh; h1l[c * H1W + p] = vl;
    }
    if (tid < 64) s_bias[tid] = bias[tid];
    __syncthreads();

    const int g = lane >> 2, tig = lane & 3;
    float C[4][4][4];
#pragma unroll
    for (int mt = 0; mt < 4; mt++)
#pragma unroll
        for (int nt = 0; nt < 4; nt++)
#pragma unroll
            for (int u = 0; u < 4; u++) C[mt][nt][u] = 0.f;

    for (int kt = 0; kt < 10; kt++) {
        const int kb = kt * 16;
        uint32_t ah[4][4], al[4][4];
#pragma unroll
        for (int mt = 0; mt < 4; mt++) {
            int r0 = (mt * 16 + g) * WST + kb + tig * 2;
            ah[mt][0] = *(const uint32_t*)&swh[r0];
            ah[mt][1] = *(const uint32_t*)&swh[r0 + 8 * WST];
            ah[mt][2] = *(const uint32_t*)&swh[r0 + 8];
            ah[mt][3] = *(const uint32_t*)&swh[r0 + 8 * WST + 8];
            al[mt][0] = *(const uint32_t*)&swl[r0];
            al[mt][1] = *(const uint32_t*)&swl[r0 + 8 * WST];
            al[mt][2] = *(const uint32_t*)&swl[r0 + 8];
            al[mt][3] = *(const uint32_t*)&swl[r0 + 8 * WST + 8];
        }
        const int k0 = kb + tig * 2;
        const int cA = k0 / 5, kkA = k0 - cA * 5;
        const int kB = k0 + 8;
        const int cB = kB / 5, kkB = kB - cB * 5;
        const int loA = cA * H1W + kkA;
        const int hiA = (kkA == 4) ? (cA + 1) * H1W : loA + 1;
        const int loB = cB * H1W + kkB;
        const int hiB = (kkB == 4) ? (cB + 1) * H1W : loB + 1;
#pragma unroll
        for (int nt = 0; nt < 4; nt++) {
            const int pos = warp * 32 + nt * 8 + g;
            uint32_t b0h = (uint32_t)h1h[loA + pos] | ((uint32_t)h1h[hiA + pos] << 16);
            uint32_t b1h = (uint32_t)h1h[loB + pos] | ((uint32_t)h1h[hiB + pos] << 16);
            uint32_t b0l = (uint32_t)h1l[loA + pos] | ((uint32_t)h1l[hiA + pos] << 16);
            uint32_t b1l = (uint32_t)h1l[loB + pos] | ((uint32_t)h1l[hiB + pos] << 16);
#pragma unroll
            for (int mt = 0; mt < 4; mt++) {
                MMA(C[mt][nt], ah[mt], b0h, b1h);
                MMA(C[mt][nt], al[mt], b0h, b1h);
                MMA(C[mt][nt], ah[mt], b0l, b1l);
            }
        }
    }
    __syncthreads();

    float* h2s = (float*)c2sm;  // [64][65], overlays h1 region
#pragma unroll
    for (int mt = 0; mt < 4; mt++) {
        int oc = mt * 16 + g;
        float bi = s_bias[oc], bi2 = s_bias[oc + 8];
#pragma unroll
        for (int nt = 0; nt < 4; nt++) {
            int node = warp * 16 + nt * 4 + tig;
            float p0 = fmaxf(fmaxf(C[mt][nt][0] + bi, 0.f), fmaxf(C[mt][nt][1] + bi, 0.f));
            float p1 = fmaxf(fmaxf(C[mt][nt][2] + bi2, 0.f), fmaxf(C[mt][nt][3] + bi2, 0.f));
            h2s[node * 65 + oc] = p0;
            h2s[node * 65 + oc + 8] = p1;
        }
    }
    for (int i = tid; i < 1024; i += 128) {
        int o = i >> 6, dd = i & 63;
        s_wt[dd * 16 + o] = gw[i];
    }
    __syncthreads();

    const int node = tid & 63, hf = tid >> 6;
    const float4* wt4 = (const float4*)s_wt;
    float acc[8] = {0,0,0,0,0,0,0,0};
#pragma unroll 4
    for (int dd = 0; dd < 64; dd++) {
        float v = h2s[node * 65 + dd];
        float4 wa = wt4[dd*4 + hf*2], wb = wt4[dd*4 + hf*2 + 1];
        acc[0]+=v*wa.x; acc[1]+=v*wa.y; acc[2]+=v*wa.z; acc[3]+=v*wa.w;
        acc[4]+=v*wb.x; acc[5]+=v*wb.y; acc[6]+=v*wb.z; acc[7]+=v*wb.w;
    }
    const int ngl = blockIdx.x * 64 + node;
    float4* outp = (float4*)&g_hw[((size_t)b * NN + ngl) * DG];
    outp[hf*2]   = make_float4(acc[0], acc[1], acc[2], acc[3]);
    outp[hf*2+1] = make_float4(acc[4], acc[5], acc[6], acc[7]);
    float ps = 0.f, pd = 0.f;
#pragma unroll
    for (int u = 0; u < 8; u++) {
        ps += acc[u] * __ldg(&asrc[hf*8+u]);
        pd += acc[u] * __ldg(&adst[hf*8+u]);
    }
    s_red[0][node][hf] = ps; s_red[1][node][hf] = pd;
    __syncthreads();
    if (tid < 64) {
        g_ssrc[b*NN + blockIdx.x*64 + tid] = s_red[0][tid][0] + s_red[0][tid][1];
        g_sdst[b*NN + blockIdx.x*64 + tid] = s_red[1][tid][0] + s_red[1][tid][1];
    }
}

// factorized GAT + mean + FC (unchanged R12)
struct GatSmem {
    float key[NN]; int idx[NN];
    float scan[17][1090]; float wtot[17][2];
    float wred[32][DG]; float pooled[DG];
};

__global__ __launch_bounds__(1024) void k_gat2(const float* __restrict__ gat_b,
                                               const float* __restrict__ fcw,
                                               const float* __restrict__ fcb,
                                               float* __restrict__ out) {
    extern __shared__ __align__(16) char smraw[];
    GatSmem& sm = *reinterpret_cast<GatSmem*>(smraw);
    const int b = blockIdx.x, tid = threadIdx.x;
    sm.key[tid] = g_ssrc[b * NN + tid];
    sm.idx[tid] = tid;
    for (int k = 2; k <= NN; k <<= 1) {
        for (int j = k >> 1; j > 0; j >>= 1) {
            __syncthreads();
            int pr = tid ^ j;
            if (pr > tid) {
                bool up = ((tid & k) == 0);
                float k0 = sm.key[tid], k1 = sm.key[pr];
                if ((k0 > k1) == up) {
                    sm.key[tid] = k1; sm.key[pr] = k0;
                    int t0 = sm.idx[tid]; sm.idx[tid] = sm.idx[pr]; sm.idx[pr] = t0;
                }
            }
        }
    }
    __syncthreads();
    const float Mss = sm.key[NN - 1];
    const int i = tid;
    const float sd = g_sdst[b * NN + i], ssi = g_ssrc[b * NN + i];
    const float msd = sd + Mss;
    const float m = (msd >= 0.f) ? msd : 0.2f * msd;
    int lo = 0, hi = NN;
    {
        const float thr = -sd;
        while (lo < hi) { int mid = (lo + hi) >> 1; if (sm.key[mid] < thr) lo = mid + 1; else hi = mid; }
    }
    const int kthx = IDXf(lo), tix = IDXf(tid);
    const int sr = tid >> 6, sc = tid & 63, lane = sc & 31, wir = sc >> 5, rb = sc * 17;
    float num[16], den;

    { // Phase B store
        float bj = __expf(0.2f * (sm.key[tid] - Mss));
        const float4* hp = (const float4*)&g_hw[((size_t)b * NN + sm.idx[tid]) * DG];
        float4 h0 = hp[0], h1 = hp[1], h2 = hp[2], h3 = hp[3];
        sm.scan[0][tix]=bj*h0.x; sm.scan[1][tix]=bj*h0.y; sm.scan[2][tix]=bj*h0.z; sm.scan[3][tix]=bj*h0.w;
        sm.scan[4][tix]=bj*h1.x; sm.scan[5][tix]=bj*h1.y; sm.scan[6][tix]=bj*h1.z; sm.scan[7][tix]=bj*h1.w;
        sm.scan[8][tix]=bj*h2.x; sm.scan[9][tix]=bj*h2.y; sm.scan[10][tix]=bj*h2.z; sm.scan[11][tix]=bj*h2.w;
        sm.scan[12][tix]=bj*h3.x; sm.scan[13][tix]=bj*h3.y; sm.scan[14][tix]=bj*h3.z; sm.scan[15][tix]=bj*h3.w;
        sm.scan[16][tix]=bj;
    }
    __syncthreads();
    { // prefix scan
        float* row = sm.scan[sr];
        float s = 0.f;
#pragma unroll
        for (int u = 0; u < 16; u++) s += row[rb + u];
        float inc = s;
#pragma unroll
        for (int o = 1; o < 32; o <<= 1) {
            float v = __shfl_up_sync(0xffffffffu, inc, o);
            if (lane >= o) inc += v;
        }
        if (lane == 31) sm.wtot[sr][wir] = inc;
        float s2 = 0.f, inc2 = 0.f;
        if (tid < 64) {
            float* dr = sm.scan[16]; int db = tid * 17;
#pragma unroll
            for (int u = 0; u < 16; u++) s2 += dr[db + u];
            inc2 = s2;
#pragma unroll
            for (int o = 1; o < 32; o <<= 1) {
                float v = __shfl_up_sync(0xffffffffu, inc2, o);
                if ((tid & 31) >= o) inc2 += v;
            }
            if ((tid & 31) == 31) sm.wtot[16][tid >> 5] = inc2;
        }
        __syncthreads();
        float off = inc - s + ((wir == 1) ? sm.wtot[sr][0] : 0.f);
        float acc = off;
#pragma unroll
        for (int u = 0; u < 16; u++) { float t = row[rb+u]; row[rb+u] = acc; acc += t; }
        if (sc == 63) row[IDXf(NN)] = acc;
        if (tid < 64) {
            float* dr = sm.scan[16]; int db = tid * 17;
            float off2 = inc2 - s2 + ((tid >= 32) ? sm.wtot[16][0] : 0.f);
            float a2 = off2;
#pragma unroll
            for (int u = 0; u < 16; u++) { float t = dr[db+u]; dr[db+u] = a2; a2 += t; }
            if (tid == 63) dr[IDXf(NN)] = a2;
        }
    }
    __syncthreads();
    {
        float wB = __expf(0.2f * msd - m);
#pragma unroll
        for (int o = 0; o < 16; o++) num[o] = wB * sm.scan[o][kthx];
        den = wB * sm.scan[16][kthx];
    }
    __syncthreads();
    { // Phase A store
        float aj = __expf(sm.key[tid] - Mss);
        const float4* hp = (const float4*)&g_hw[((size_t)b * NN + sm.idx[tid]) * DG];
        float4 h0 = hp[0], h1 = hp[1], h2 = hp[2], h3 = hp[3];
        sm.scan[0][tix]=aj*h0.x; sm.scan[1][tix]=aj*h0.y; sm.scan[2][tix]=aj*h0.z; sm.scan[3][tix]=aj*h0.w;
        sm.scan[4][tix]=aj*h1.x; sm.scan[5][tix]=aj*h1.y; sm.scan[6][tix]=aj*h1.z; sm.scan[7][tix]=aj*h1.w;
        sm.scan[8][tix]=aj*h2.x; sm.scan[9][tix]=aj*h2.y; sm.scan[10][tix]=aj*h2.z; sm.scan[11][tix]=aj*h2.w;
        sm.scan[12][tix]=aj*h3.x; sm.scan[13][tix]=aj*h3.y; sm.scan[14][tix]=aj*h3.z; sm.scan[15][tix]=aj*h3.w;
        sm.scan[16][tix]=aj;
    }
    __syncthreads();
    { // suffix scan
        float* row = sm.scan[sr];
        float s = 0.f;
#pragma unroll
        for (int u = 0; u < 16; u++) s += row[rb + u];
        float inc = s;
#pragma unroll
        for (int o = 1; o < 32; o <<= 1) {
            float v = __shfl_down_sync(0xffffffffu, inc, o);
            if (lane < 32 - o) inc += v;
        }
        if (lane == 0) sm.wtot[sr][wir] = inc;
        float s2 = 0.f, inc2 = 0.f;
        if (tid < 64) {
            float* dr = sm.scan[16]; int db = tid * 17;
#pragma unroll
            for (int u = 0; u < 16; u++) s2 += dr[db + u];
            inc2 = s2;
#pragma unroll
            for (int o = 1; o < 32; o <<= 1) {
                float v = __shfl_down_sync(0xffffffffu, inc2, o);
                if ((tid & 31) < 32 - o) inc2 += v;
            }
            if ((tid & 31) == 0) sm.wtot[16][tid >> 5] = inc2;
        }
        __syncthreads();
        float off = inc - s + ((wir == 0) ? sm.wtot[sr][1] : 0.f);
        float acc = off;
#pragma unroll
        for (int u = 15; u >= 0; u--) { acc += row[rb+u]; row[rb+u] = acc; }
        if (sc == 63) row[IDXf(NN)] = 0.f;
        if (tid < 64) {
            float* dr = sm.scan[16]; int db = tid * 17;
            float off2 = inc2 - s2 + ((tid < 32) ? sm.wtot[16][1] : 0.f);
            float a2 = off2;
#pragma unroll
            for (int u = 15; u >= 0; u--) { a2 += dr[db+u]; dr[db+u] = a2; }
            if (tid == 63) dr[IDXf(NN)] = 0.f;
        }
    }
    __syncthreads();
    {
        float wA = __expf(msd - m);
#pragma unroll
        for (int o = 0; o < 16; o++) num[o] += wA * sm.scan[o][kthx];
        den += wA * sm.scan[16][kthx];
    }
    { // duplicated self-loop
        float e = sd + ssi;
        e = (e >= 0.f) ? e : 0.2f * e;
        float ws = __expf(e - m);
        den += ws;
        const float4* hp = (const float4*)&g_hw[((size_t)b * NN + i) * DG];
        float4 h0 = hp[0], h1 = hp[1], h2 = hp[2], h3 = hp[3];
        num[0]+=ws*h0.x; num[1]+=ws*h0.y; num[2]+=ws*h0.z; num[3]+=ws*h0.w;
        num[4]+=ws*h1.x; num[5]+=ws*h1.y; num[6]+=ws*h1.z; num[7]+=ws*h1.w;
        num[8]+=ws*h2.x; num[9]+=ws*h2.y; num[10]+=ws*h2.z; num[11]+=ws*h2.w;
        num[12]+=ws*h3.x; num[13]+=ws*h3.y; num[14]+=ws*h3.z; num[15]+=ws*h3.w;
    }
    const float inv = 1.f / den;
#pragma unroll
    for (int o = 0; o < 16; o++) num[o] *= inv;
#pragma unroll
    for (int o = 0; o < 16; o++) {
        float v = num[o];
        v += __shfl_xor_sync(0xffffffffu, v, 16);
        v += __shfl_xor_sync(0xffffffffu, v, 8);
        v += __shfl_xor_sync(0xffffffffu, v, 4);
        v += __shfl_xor_sync(0xffffffffu, v, 2);
        v += __shfl_xor_sync(0xffffffffu, v, 1);
        if ((tid & 31) == 0) sm.wred[tid >> 5][o] = v;
    }
    __syncthreads();
    if (tid < 16) {
        float s = 0.f;
        for (int w = 0; w < 32; w++) s += sm.wred[w][tid];
        sm.pooled[tid] = s * (1.0f / (float)NN) + __ldg(&gat_b[tid]);
    }
    __syncthreads();
    if (tid < 2) {
        float r = __ldg(&fcb[tid]);
#pragma unroll
        for (int o = 0; o < 16; o++) r += sm.pooled[o] * __ldg(&fcw[tid * 16 + o]);
        out[b * 2 + tid] = r;
    }
}

extern "C" void kernel_launch(void* const* d_in, const int* in_sizes, int n_in,
                              void* d_out, int out_size) {
    const float* x    = (const float*)d_in[0];
    const float* c1w  = (const float*)d_in[1];
    const float* c1b  = (const float*)d_in[2];
    const float* c2w  = (const float*)d_in[3];
    const float* c2b  = (const float*)d_in[4];
    const float* gw   = (const float*)d_in[5];
    const float* asrc = (const float*)d_in[6];
    const float* adst = (const float*)d_in[7];
    const float* gb   = (const float*)d_in[8];
    const float* fcw  = (const float*)d_in[9];
    const float* fcb  = (const float*)d_in[10];
    float* out = (float*)d_out;

    k_conv1<<<dim3(32, BATCH), 128>>>(x, c1w, c1b);
    k_prep<<<40, 256>>>(c2w);
    cudaFuncSetAttribute(k_conv2_mma, cudaFuncAttributeMaxDynamicSharedMemorySize, C2SM_TOT);
    k_conv2_mma<<<dim3(16, BATCH), 128, C2SM_TOT>>>(c2b, gw, asrc, adst);
    cudaFuncSetAttribute(k_gat2, cudaFuncAttributeMaxDynamicSharedMemorySize,
                         (int)sizeof(GatSmem));
    k_gat2<<<BATCH, 1024, sizeof(GatSmem)>>>(gb, fcw, fcb, out);
}